// round 1
// baseline (speedup 1.0000x reference)
#include <cuda_runtime.h>

#define W 256
#define H 256
#define BATCH 64
#define NF 8
#define KS 15
#define PAD 7

#define TILE_X 32
#define TILE_Y 64
#define SROWS (TILE_Y + KS - 1)   // 78
#define SCOLS (TILE_X + KS - 1)   // 46
#define SSTRIDE 48

// scratch: summed input (16 MB) and gabor weights [tap][filter]
__device__ float g_xs[BATCH * H * W];
__device__ float g_w[KS * KS * NF];

// ---------------------------------------------------------------------------
// Kernel A: build the 8 Gabor kernels. One warp per filter.
// ---------------------------------------------------------------------------
__global__ void gabor_weights_kernel(const float* __restrict__ theta,
                                     const float* __restrict__ sigma,
                                     const float* __restrict__ lambd,
                                     const float* __restrict__ gamma,
                                     const float* __restrict__ psi) {
    int warp = threadIdx.x >> 5;
    int lane = threadIdx.x & 31;
    if (warp >= NF) return;
    int f = warp;

    float th = theta[f];
    float sg = fmaxf(sigma[f], 1.0f);
    float lb = fmaxf(lambd[f], 2.0f);
    float gm = fminf(fmaxf(gamma[f], 0.1f), 1.0f);
    float ps = psi[f];
    float ct = cosf(th), st = sinf(th);
    const float TWO_PI = 6.283185307179586f;
    float inv_sg2 = 1.0f / (sg * sg);
    float gm2 = gm * gm;

    float vals[8];
    float sum = 0.0f;
    #pragma unroll
    for (int k = 0; k < 8; k++) {
        int i = lane + 32 * k;
        float v = 0.0f;
        if (i < KS * KS) {
            int hh = i / KS, ww = i % KS;
            float y = (float)(hh - PAD);
            float x = (float)(ww - PAD);
            float xt = x * ct + y * st;
            float yt = -x * st + y * ct;
            float gaussian = expf(-0.5f * (xt * xt + gm2 * yt * yt) * inv_sg2);
            float sinus = cosf(TWO_PI * xt / lb + ps);
            v = gaussian * sinus;
        }
        vals[k] = v;
        sum += v;
    }
    #pragma unroll
    for (int o = 16; o; o >>= 1) sum += __shfl_xor_sync(0xffffffffu, sum, o);
    float mean = sum * (1.0f / 225.0f);

    float ss = 0.0f;
    #pragma unroll
    for (int k = 0; k < 8; k++) {
        int i = lane + 32 * k;
        if (i < KS * KS) {
            float d = vals[k] - mean;
            ss += d * d;
        }
    }
    #pragma unroll
    for (int o = 16; o; o >>= 1) ss += __shfl_xor_sync(0xffffffffu, ss, o);
    float inv = 1.0f / (sqrtf(ss * (1.0f / 224.0f)) + 1e-8f);

    #pragma unroll
    for (int k = 0; k < 8; k++) {
        int i = lane + 32 * k;
        if (i < KS * KS) g_w[i * NF + f] = (vals[k] - mean) * inv;
    }
}

// ---------------------------------------------------------------------------
// Kernel B: channel sum (3 -> 1), float4 vectorized.
// ---------------------------------------------------------------------------
__global__ void chansum_kernel(const float* __restrict__ x) {
    int i = blockIdx.x * blockDim.x + threadIdx.x;   // float4 index
    const int plane4 = H * W / 4;                    // 16384
    const int n4 = BATCH * plane4;
    if (i >= n4) return;
    int b = i / plane4;
    int p = i - b * plane4;
    const float4* xb = (const float4*)x + (size_t)b * 3 * plane4;
    float4 a = xb[p];
    float4 c = xb[p + plane4];
    float4 d = xb[p + 2 * plane4];
    float4 r;
    r.x = a.x + c.x + d.x;
    r.y = a.y + c.y + d.y;
    r.z = a.z + c.z + d.z;
    r.w = a.w + c.w + d.w;
    ((float4*)g_xs)[i] = r;
}

// ---------------------------------------------------------------------------
// Kernel C: 15x15 conv, 8 filters, fp32 packed f32x2 (filter pairs in vector lanes).
// Block (32,8) = 256 threads. Tile: 32 cols x 64 rows.
// Thread (tx,ty): col tx, rows ty*8 + p (p=0..7), all 8 filters.
// ---------------------------------------------------------------------------
__global__ void __launch_bounds__(256, 2)
gabor_conv_kernel(float* __restrict__ out) {
    __shared__ __align__(16) float s_in[SROWS * SSTRIDE];   // 78*48 floats
    __shared__ __align__(16) float s_w[KS * KS * NF];       // 1800 floats

    int tx = threadIdx.x;
    int ty = threadIdx.y;
    int tid = tx + ty * 32;
    int x0 = blockIdx.x * TILE_X;
    int y0 = blockIdx.y * TILE_Y;
    int b  = blockIdx.z;

    // load weights
    for (int i = tid; i < KS * KS * NF; i += 256) s_w[i] = g_w[i];

    // load input tile with halo (zero-padded)
    const float* xs = g_xs + (size_t)b * H * W;
    for (int i = tid; i < SROWS * SCOLS; i += 256) {
        int r = i / SCOLS, c = i - r * SCOLS;
        int gy = y0 - PAD + r;
        int gx = x0 - PAD + c;
        float v = 0.0f;
        if (gy >= 0 && gy < H && gx >= 0 && gx < W) v = xs[gy * W + gx];
        s_in[r * SSTRIDE + c] = v;
    }
    __syncthreads();

    // 32 packed accumulators: [pixel p][filter pair q]
    unsigned long long acc[8][4];
    #pragma unroll
    for (int p = 0; p < 8; p++)
        #pragma unroll
        for (int q = 0; q < 4; q++) acc[p][q] = 0ull;

    #pragma unroll 1
    for (int ky = 0; ky < KS; ky++) {
        const ulonglong2* wrow = (const ulonglong2*)(s_w + ky * KS * NF);
        const float* in0 = s_in + (ty * 8 + ky) * SSTRIDE + tx;
        #pragma unroll
        for (int kx = 0; kx < KS; kx++) {
            ulonglong2 w01 = wrow[kx * 2];       // filters 0,1 | 2,3
            ulonglong2 w23 = wrow[kx * 2 + 1];   // filters 4,5 | 6,7
            #pragma unroll
            for (int p = 0; p < 8; p++) {
                float v = in0[p * SSTRIDE + kx];
                unsigned long long vv;
                asm("mov.b64 %0, {%1, %2};" : "=l"(vv) : "f"(v), "f"(v));
                asm("fma.rn.f32x2 %0, %1, %2, %0;" : "+l"(acc[p][0]) : "l"(vv), "l"(w01.x));
                asm("fma.rn.f32x2 %0, %1, %2, %0;" : "+l"(acc[p][1]) : "l"(vv), "l"(w01.y));
                asm("fma.rn.f32x2 %0, %1, %2, %0;" : "+l"(acc[p][2]) : "l"(vv), "l"(w23.x));
                asm("fma.rn.f32x2 %0, %1, %2, %0;" : "+l"(acc[p][3]) : "l"(vv), "l"(w23.y));
            }
        }
    }

    // store: out[b][f][y][x]
    float* ob = out + (size_t)b * NF * H * W;
    int x = x0 + tx;
    #pragma unroll
    for (int p = 0; p < 8; p++) {
        int y = y0 + ty * 8 + p;
        int base = y * W + x;
        #pragma unroll
        for (int q = 0; q < 4; q++) {
            float lo, hi;
            asm("mov.b64 {%0, %1}, %2;" : "=f"(lo), "=f"(hi) : "l"(acc[p][q]));
            ob[(2 * q) * H * W + base] = lo;
            ob[(2 * q + 1) * H * W + base] = hi;
        }
    }
}

// ---------------------------------------------------------------------------
extern "C" void kernel_launch(void* const* d_in, const int* in_sizes, int n_in,
                              void* d_out, int out_size) {
    const float* x     = (const float*)d_in[0];
    const float* theta = (const float*)d_in[1];
    const float* sigma = (const float*)d_in[2];
    const float* lambd = (const float*)d_in[3];
    const float* gamma = (const float*)d_in[4];
    const float* psi   = (const float*)d_in[5];
    float* out = (float*)d_out;

    gabor_weights_kernel<<<1, 256>>>(theta, sigma, lambd, gamma, psi);

    int n4 = BATCH * H * W / 4;
    chansum_kernel<<<(n4 + 255) / 256, 256>>>(x);

    dim3 blk(32, 8);
    dim3 grd(W / TILE_X, H / TILE_Y, BATCH);
    gabor_conv_kernel<<<grd, blk>>>(out);
}

// round 2
// speedup vs baseline: 1.1899x; 1.1899x over previous
#include <cuda_runtime.h>

#define W 256
#define H 256
#define BATCH 64
#define NF 8
#define KS 15
#define PAD 7

#define TILE_X 64           // 8 threads x 8 px
#define TILE_Y 32
#define SROWS (TILE_Y + KS - 1)   // 46
#define SCOLS (TILE_X + KS - 1)   // 78
#define SSTRIDE 80

#define CHAN_BLOCKS 4096    // chansum float4 blocks; block CHAN_BLOCKS does weights

__device__ float g_xs[BATCH * H * W];
__device__ float g_w[KS * KS * NF];   // [tap][filter]

// ---------------------------------------------------------------------------
// Kernel A+B merged: blocks [0, CHAN_BLOCKS) do channel-sum; block CHAN_BLOCKS
// computes the 8 Gabor kernels (one warp per filter).
// ---------------------------------------------------------------------------
__global__ void prep_kernel(const float* __restrict__ x,
                            const float* __restrict__ theta,
                            const float* __restrict__ sigma,
                            const float* __restrict__ lambd,
                            const float* __restrict__ gamma,
                            const float* __restrict__ psi) {
    if (blockIdx.x < CHAN_BLOCKS) {
        // channel sum (3 -> 1), float4
        int i = blockIdx.x * blockDim.x + threadIdx.x;
        const int plane4 = H * W / 4;
        int b = i / plane4;
        int p = i - b * plane4;
        const float4* xb = (const float4*)x + (size_t)b * 3 * plane4;
        float4 a = xb[p];
        float4 c = xb[p + plane4];
        float4 d = xb[p + 2 * plane4];
        float4 r;
        r.x = a.x + c.x + d.x;
        r.y = a.y + c.y + d.y;
        r.z = a.z + c.z + d.z;
        r.w = a.w + c.w + d.w;
        ((float4*)g_xs)[i] = r;
        return;
    }

    // ---- Gabor weights: one warp per filter ----
    int warp = threadIdx.x >> 5;
    int lane = threadIdx.x & 31;
    if (warp >= NF) return;
    int f = warp;

    float th = theta[f];
    float sg = fmaxf(sigma[f], 1.0f);
    float lb = fmaxf(lambd[f], 2.0f);
    float gm = fminf(fmaxf(gamma[f], 0.1f), 1.0f);
    float ps = psi[f];
    float ct = cosf(th), st = sinf(th);
    const float TWO_PI = 6.283185307179586f;
    float inv_sg2 = 1.0f / (sg * sg);
    float gm2 = gm * gm;

    float vals[8];
    float sum = 0.0f;
    #pragma unroll
    for (int k = 0; k < 8; k++) {
        int i = lane + 32 * k;
        float v = 0.0f;
        if (i < KS * KS) {
            int hh = i / KS, ww = i % KS;
            float y = (float)(hh - PAD);
            float xx = (float)(ww - PAD);
            float xt = xx * ct + y * st;
            float yt = -xx * st + y * ct;
            float gaussian = expf(-0.5f * (xt * xt + gm2 * yt * yt) * inv_sg2);
            float sinus = cosf(TWO_PI * xt / lb + ps);
            v = gaussian * sinus;
        }
        vals[k] = v;
        sum += v;
    }
    #pragma unroll
    for (int o = 16; o; o >>= 1) sum += __shfl_xor_sync(0xffffffffu, sum, o);
    float mean = sum * (1.0f / 225.0f);

    float ss = 0.0f;
    #pragma unroll
    for (int k = 0; k < 8; k++) {
        int i = lane + 32 * k;
        if (i < KS * KS) {
            float d = vals[k] - mean;
            ss += d * d;
        }
    }
    #pragma unroll
    for (int o = 16; o; o >>= 1) ss += __shfl_xor_sync(0xffffffffu, ss, o);
    float inv = 1.0f / (sqrtf(ss * (1.0f / 224.0f)) + 1e-8f);

    #pragma unroll
    for (int k = 0; k < 8; k++) {
        int i = lane + 32 * k;
        if (i < KS * KS) g_w[i * NF + f] = (vals[k] - mean) * inv;
    }
}

// ---------------------------------------------------------------------------
// Conv kernel: 15x15, 8 filters, packed f32x2 (filter pairs in vector lanes).
// Block (8,32) = 256 threads, tile 64x32. Thread (txq,tyr): row y0+tyr,
// pixels x0 + txq*8 + p (p = 0..7), all 8 filters.
// Per ky: 6 LDS.128 input (24 floats), 22 hoisted (v,v) packs,
// 30 broadcast weight LDS.128, 480 FFMA2.
// ---------------------------------------------------------------------------
__global__ void __launch_bounds__(256, 2)
gabor_conv_kernel(float* __restrict__ out) {
    __shared__ __align__(16) float s_in[SROWS * SSTRIDE];   // 46*80
    __shared__ __align__(16) float s_w[KS * KS * NF];       // 1800

    int txq = threadIdx.x;            // 0..7
    int tyr = threadIdx.y;            // 0..31
    int tid = txq + tyr * 8;
    int x0 = blockIdx.x * TILE_X;
    int y0 = blockIdx.y * TILE_Y;
    int b  = blockIdx.z;

    // load weights
    for (int i = tid; i < KS * KS * NF; i += 256) s_w[i] = g_w[i];

    // load input tile + halo (zero-padded)
    const float* xs = g_xs + (size_t)b * H * W;
    for (int i = tid; i < SROWS * SCOLS; i += 256) {
        int r = i / SCOLS, c = i - r * SCOLS;
        int gy = y0 - PAD + r;
        int gx = x0 - PAD + c;
        float v = 0.0f;
        if (gy >= 0 && gy < H && gx >= 0 && gx < W) v = xs[gy * W + gx];
        s_in[r * SSTRIDE + c] = v;
    }
    __syncthreads();

    // acc[p][q]: pixel p (x0+txq*8+p), filter pair q -> filters (2q, 2q+1)
    unsigned long long acc[8][4];
    #pragma unroll
    for (int p = 0; p < 8; p++)
        #pragma unroll
        for (int q = 0; q < 4; q++) acc[p][q] = 0ull;

    #pragma unroll 1
    for (int ky = 0; ky < KS; ky++) {
        // 24 input floats for this thread's kx window
        const float4* ip = (const float4*)(s_in + (tyr + ky) * SSTRIDE + txq * 8);
        float xv[24];
        #pragma unroll
        for (int j = 0; j < 6; j++) {
            float4 t = ip[j];
            xv[4 * j + 0] = t.x;
            xv[4 * j + 1] = t.y;
            xv[4 * j + 2] = t.z;
            xv[4 * j + 3] = t.w;
        }
        // hoisted broadcast packs: only 22 distinct (v,v) values
        unsigned long long vb[22];
        #pragma unroll
        for (int j = 0; j < 22; j++)
            asm("mov.b64 %0, {%1, %1};" : "=l"(vb[j]) : "f"(xv[j]));

        const ulonglong2* wrow = (const ulonglong2*)(s_w + ky * KS * NF);
        #pragma unroll
        for (int kx = 0; kx < KS; kx++) {
            ulonglong2 w01 = wrow[2 * kx];       // filters (0,1) | (2,3)
            ulonglong2 w23 = wrow[2 * kx + 1];   // filters (4,5) | (6,7)
            #pragma unroll
            for (int p = 0; p < 8; p++) {
                asm("fma.rn.f32x2 %0, %1, %2, %0;" : "+l"(acc[p][0]) : "l"(vb[p + kx]), "l"(w01.x));
                asm("fma.rn.f32x2 %0, %1, %2, %0;" : "+l"(acc[p][1]) : "l"(vb[p + kx]), "l"(w01.y));
                asm("fma.rn.f32x2 %0, %1, %2, %0;" : "+l"(acc[p][2]) : "l"(vb[p + kx]), "l"(w23.x));
                asm("fma.rn.f32x2 %0, %1, %2, %0;" : "+l"(acc[p][3]) : "l"(vb[p + kx]), "l"(w23.y));
            }
        }
    }

    // unpack and store: out[b][f][y][x], coalesced STG.128
    float r[8][8];   // [p][f]
    #pragma unroll
    for (int p = 0; p < 8; p++)
        #pragma unroll
        for (int q = 0; q < 4; q++)
            asm("mov.b64 {%0, %1}, %2;"
                : "=f"(r[p][2 * q]), "=f"(r[p][2 * q + 1]) : "l"(acc[p][q]));

    float* ob = out + (size_t)b * NF * H * W;
    int xbase = x0 + txq * 8;
    int y = y0 + tyr;
    #pragma unroll
    for (int f = 0; f < NF; f++) {
        float4* dst = (float4*)(ob + f * H * W + y * W + xbase);
        float4 v0 = make_float4(r[0][f], r[1][f], r[2][f], r[3][f]);
        float4 v1 = make_float4(r[4][f], r[5][f], r[6][f], r[7][f]);
        dst[0] = v0;
        dst[1] = v1;
    }
}

// ---------------------------------------------------------------------------
extern "C" void kernel_launch(void* const* d_in, const int* in_sizes, int n_in,
                              void* d_out, int out_size) {
    const float* x     = (const float*)d_in[0];
    const float* theta = (const float*)d_in[1];
    const float* sigma = (const float*)d_in[2];
    const float* lambd = (const float*)d_in[3];
    const float* gamma = (const float*)d_in[4];
    const float* psi   = (const float*)d_in[5];
    float* out = (float*)d_out;

    prep_kernel<<<CHAN_BLOCKS + 1, 256>>>(x, theta, sigma, lambd, gamma, psi);

    dim3 blk(8, 32);
    dim3 grd(W / TILE_X, H / TILE_Y, BATCH);
    gabor_conv_kernel<<<grd, blk>>>(out);
}

// round 3
// speedup vs baseline: 1.8986x; 1.5957x over previous
#include <cuda_runtime.h>

#define W 256
#define H 256
#define BATCH 64
#define NF 8
#define KS 15
#define PAD 7

#define TILE_X 64           // 16 threads x 4 px
#define TILE_Y 16
#define SROWS (TILE_Y + KS - 1)   // 30
#define SCOLS (TILE_X + KS - 1)   // 78
#define SSTRIDE 80

#define NPAIR 113           // 112 symmetric pairs + center

#define CHAN_BLOCKS 4096

__device__ float g_xs[BATCH * H * W];
__device__ float g_w[KS * KS * NF];    // full weights [tap][filter] (fallback)
__device__ float g_wa[NPAIR * NF];     // symmetric-pair weights [pair][filter]
__device__ int   g_flag;               // 1 -> kernels not symmetric, use fallback

// ---------------------------------------------------------------------------
// Prep: blocks [0, CHAN_BLOCKS) channel-sum; block CHAN_BLOCKS builds weights.
// ---------------------------------------------------------------------------
__global__ void prep_kernel(const float* __restrict__ x,
                            const float* __restrict__ theta,
                            const float* __restrict__ sigma,
                            const float* __restrict__ lambd,
                            const float* __restrict__ gamma,
                            const float* __restrict__ psi) {
    if (blockIdx.x < CHAN_BLOCKS) {
        int i = blockIdx.x * blockDim.x + threadIdx.x;
        const int plane4 = H * W / 4;
        int b = i / plane4;
        int p = i - b * plane4;
        const float4* xb = (const float4*)x + (size_t)b * 3 * plane4;
        float4 a = xb[p];
        float4 c = xb[p + plane4];
        float4 d = xb[p + 2 * plane4];
        float4 r;
        r.x = a.x + c.x + d.x;
        r.y = a.y + c.y + d.y;
        r.z = a.z + c.z + d.z;
        r.w = a.w + c.w + d.w;
        ((float4*)g_xs)[i] = r;
        return;
    }

    // ---- Gabor weights ----
    __shared__ float s_w[NF][228];
    __shared__ int sflag;
    int tid = threadIdx.x;
    int warp = tid >> 5;
    int lane = tid & 31;
    if (tid == 0) sflag = 0;

    if (warp < NF) {
        int f = warp;
        float th = theta[f];
        float sg = fmaxf(sigma[f], 1.0f);
        float lb = fmaxf(lambd[f], 2.0f);
        float gm = fminf(fmaxf(gamma[f], 0.1f), 1.0f);
        float ps = psi[f];
        float ct = cosf(th), st = sinf(th);
        const float TWO_PI = 6.283185307179586f;
        float inv_sg2 = 1.0f / (sg * sg);
        float gm2 = gm * gm;

        float vals[8];
        float sum = 0.0f;
        #pragma unroll
        for (int k = 0; k < 8; k++) {
            int i = lane + 32 * k;
            float v = 0.0f;
            if (i < KS * KS) {
                int hh = i / KS, ww = i % KS;
                float y = (float)(hh - PAD);
                float xx = (float)(ww - PAD);
                float xt = xx * ct + y * st;
                float yt = -xx * st + y * ct;
                float gaussian = expf(-0.5f * (xt * xt + gm2 * yt * yt) * inv_sg2);
                float sinus = cosf(TWO_PI * xt / lb + ps);
                v = gaussian * sinus;
            }
            vals[k] = v;
            sum += v;
        }
        #pragma unroll
        for (int o = 16; o; o >>= 1) sum += __shfl_xor_sync(0xffffffffu, sum, o);
        float mean = sum * (1.0f / 225.0f);

        float ss = 0.0f;
        #pragma unroll
        for (int k = 0; k < 8; k++) {
            int i = lane + 32 * k;
            if (i < KS * KS) {
                float d = vals[k] - mean;
                ss += d * d;
            }
        }
        #pragma unroll
        for (int o = 16; o; o >>= 1) ss += __shfl_xor_sync(0xffffffffu, ss, o);
        float inv = 1.0f / (sqrtf(ss * (1.0f / 224.0f)) + 1e-8f);

        #pragma unroll
        for (int k = 0; k < 8; k++) {
            int i = lane + 32 * k;
            if (i < KS * KS) s_w[f][i] = (vals[k] - mean) * inv;
        }
    }
    __syncthreads();

    // full weights tap-major (fallback path)
    for (int idx = tid; idx < KS * KS * NF; idx += 256) {
        int i = idx >> 3, f = idx & 7;
        g_w[idx] = s_w[f][i];
    }

    // symmetric-pair weights: pair t -> linear tap i1, mirror i2 = 224-i1
    for (int idx = tid; idx < NPAIR * NF; idx += 256) {
        int t = idx >> 3, f = idx & 7;
        int i1;
        if (t < 105)      i1 = t;               // ky<7, all kx
        else if (t < 112) i1 = 105 + (t - 105); // ky==7, kx 0..6
        else              i1 = 112;             // center
        int i2 = 224 - i1;
        float w1 = s_w[f][i1], w2 = s_w[f][i2];
        float wa = (t == 112) ? w1 : 0.5f * (w1 + w2);
        float wb = (t == 112) ? 0.0f : 0.5f * (w1 - w2);
        g_wa[idx] = wa;
        if (fabsf(wb) > 1e-6f) atomicOr(&sflag, 1);
    }
    __syncthreads();
    if (tid == 0) g_flag = sflag;
}

// ---------------------------------------------------------------------------
// Fast conv: symmetric-pair path. Block (16,16), tile 64x16, 4 px/thread.
// Per pair (ky,kx): s[p] = top[p+kx] + bot[p+14-kx]  (1 FADD, rt=2),
// then 4 FFMA2 (s,s) x (filter-pair weights).
// ---------------------------------------------------------------------------
__global__ void __launch_bounds__(256, 2)
gabor_conv_sym(float* __restrict__ out) {
    if (g_flag != 0) return;   // fallback kernel handles it

    __shared__ __align__(16) float s_in[SROWS * SSTRIDE];
    __shared__ __align__(16) float s_wa[NPAIR * NF];

    int txq = threadIdx.x;        // 0..15 -> 4 px each
    int tyr = threadIdx.y;        // 0..15
    int tid = txq + tyr * 16;
    int x0 = blockIdx.x * TILE_X;
    int y0 = blockIdx.y * TILE_Y;
    int b  = blockIdx.z;

    for (int i = tid; i < NPAIR * NF; i += 256) s_wa[i] = g_wa[i];

    const float* xs = g_xs + (size_t)b * H * W;
    for (int i = tid; i < SROWS * SCOLS; i += 256) {
        int r = i / SCOLS, c = i - r * SCOLS;
        int gy = y0 - PAD + r;
        int gx = x0 - PAD + c;
        float v = 0.0f;
        if (gy >= 0 && gy < H && gx >= 0 && gx < W) v = xs[gy * W + gx];
        s_in[r * SSTRIDE + c] = v;
    }
    __syncthreads();

    int c0 = txq * 4;
    unsigned long long acc[4][4];
    #pragma unroll
    for (int p = 0; p < 4; p++)
        #pragma unroll
        for (int q = 0; q < 4; q++) acc[p][q] = 0ull;

    // ky pairs 0..6 with 14-ky
    #pragma unroll 1
    for (int kyp = 0; kyp < 7; kyp++) {
        float t[20], bo[20];
        const float4* tp = (const float4*)(s_in + (tyr + kyp) * SSTRIDE + c0);
        const float4* bp = (const float4*)(s_in + (tyr + 14 - kyp) * SSTRIDE + c0);
        #pragma unroll
        for (int j = 0; j < 5; j++) {
            float4 v = tp[j];
            t[4 * j] = v.x; t[4 * j + 1] = v.y; t[4 * j + 2] = v.z; t[4 * j + 3] = v.w;
            float4 u = bp[j];
            bo[4 * j] = u.x; bo[4 * j + 1] = u.y; bo[4 * j + 2] = u.z; bo[4 * j + 3] = u.w;
        }
        const ulonglong2* wrow = (const ulonglong2*)(s_wa + kyp * 15 * NF);
        #pragma unroll
        for (int kx = 0; kx < KS; kx++) {
            ulonglong2 w01 = wrow[2 * kx];
            ulonglong2 w23 = wrow[2 * kx + 1];
            #pragma unroll
            for (int p = 0; p < 4; p++) {
                float s = t[p + kx] + bo[p + 14 - kx];
                unsigned long long ss;
                asm("mov.b64 %0, {%1, %1};" : "=l"(ss) : "f"(s));
                asm("fma.rn.f32x2 %0, %1, %2, %0;" : "+l"(acc[p][0]) : "l"(ss), "l"(w01.x));
                asm("fma.rn.f32x2 %0, %1, %2, %0;" : "+l"(acc[p][1]) : "l"(ss), "l"(w01.y));
                asm("fma.rn.f32x2 %0, %1, %2, %0;" : "+l"(acc[p][2]) : "l"(ss), "l"(w23.x));
                asm("fma.rn.f32x2 %0, %1, %2, %0;" : "+l"(acc[p][3]) : "l"(ss), "l"(w23.y));
            }
        }
    }

    // ky == 7 row: kx pairs 0..6 plus center
    {
        float r[20];
        const float4* rp = (const float4*)(s_in + (tyr + 7) * SSTRIDE + c0);
        #pragma unroll
        for (int j = 0; j < 5; j++) {
            float4 v = rp[j];
            r[4 * j] = v.x; r[4 * j + 1] = v.y; r[4 * j + 2] = v.z; r[4 * j + 3] = v.w;
        }
        const ulonglong2* wrow = (const ulonglong2*)(s_wa + 105 * NF);
        #pragma unroll
        for (int kx = 0; kx < 7; kx++) {
            ulonglong2 w01 = wrow[2 * kx];
            ulonglong2 w23 = wrow[2 * kx + 1];
            #pragma unroll
            for (int p = 0; p < 4; p++) {
                float s = r[p + kx] + r[p + 14 - kx];
                unsigned long long ss;
                asm("mov.b64 %0, {%1, %1};" : "=l"(ss) : "f"(s));
                asm("fma.rn.f32x2 %0, %1, %2, %0;" : "+l"(acc[p][0]) : "l"(ss), "l"(w01.x));
                asm("fma.rn.f32x2 %0, %1, %2, %0;" : "+l"(acc[p][1]) : "l"(ss), "l"(w01.y));
                asm("fma.rn.f32x2 %0, %1, %2, %0;" : "+l"(acc[p][2]) : "l"(ss), "l"(w23.x));
                asm("fma.rn.f32x2 %0, %1, %2, %0;" : "+l"(acc[p][3]) : "l"(ss), "l"(w23.y));
            }
        }
        // center tap (7,7) -> pair index 112
        ulonglong2 w01 = ((const ulonglong2*)(s_wa + 112 * NF))[0];
        ulonglong2 w23 = ((const ulonglong2*)(s_wa + 112 * NF))[1];
        #pragma unroll
        for (int p = 0; p < 4; p++) {
            float v = r[p + 7];
            unsigned long long ss;
            asm("mov.b64 %0, {%1, %1};" : "=l"(ss) : "f"(v));
            asm("fma.rn.f32x2 %0, %1, %2, %0;" : "+l"(acc[p][0]) : "l"(ss), "l"(w01.x));
            asm("fma.rn.f32x2 %0, %1, %2, %0;" : "+l"(acc[p][1]) : "l"(ss), "l"(w01.y));
            asm("fma.rn.f32x2 %0, %1, %2, %0;" : "+l"(acc[p][2]) : "l"(ss), "l"(w23.x));
            asm("fma.rn.f32x2 %0, %1, %2, %0;" : "+l"(acc[p][3]) : "l"(ss), "l"(w23.y));
        }
    }

    // unpack + coalesced float4 stores
    float r[4][8];
    #pragma unroll
    for (int p = 0; p < 4; p++)
        #pragma unroll
        for (int q = 0; q < 4; q++)
            asm("mov.b64 {%0, %1}, %2;"
                : "=f"(r[p][2 * q]), "=f"(r[p][2 * q + 1]) : "l"(acc[p][q]));

    float* ob = out + (size_t)b * NF * H * W;
    int y = y0 + tyr;
    int xb = x0 + c0;
    #pragma unroll
    for (int f = 0; f < NF; f++) {
        float4 v = make_float4(r[0][f], r[1][f], r[2][f], r[3][f]);
        *(float4*)(ob + f * H * W + y * W + xb) = v;
    }
}

// ---------------------------------------------------------------------------
// Fallback: generic direct conv (runs only if weights are not symmetric).
// ---------------------------------------------------------------------------
__global__ void gabor_conv_fallback(float* __restrict__ out) {
    if (g_flag == 0) return;
    int total = BATCH * NF * H * W;
    for (int idx = blockIdx.x * blockDim.x + threadIdx.x; idx < total;
         idx += gridDim.x * blockDim.x) {
        int x = idx & (W - 1);
        int y = (idx >> 8) & (H - 1);
        int f = (idx >> 16) & (NF - 1);
        int b = idx >> 19;
        const float* xs = g_xs + (size_t)b * H * W;
        float acc = 0.0f;
        for (int ky = 0; ky < KS; ky++) {
            int gy = y - PAD + ky;
            if (gy < 0 || gy >= H) continue;
            for (int kx = 0; kx < KS; kx++) {
                int gx = x - PAD + kx;
                if (gx < 0 || gx >= W) continue;
                acc += g_w[(ky * KS + kx) * NF + f] * xs[gy * W + gx];
            }
        }
        out[idx] = acc;
    }
}

// ---------------------------------------------------------------------------
extern "C" void kernel_launch(void* const* d_in, const int* in_sizes, int n_in,
                              void* d_out, int out_size) {
    const float* x     = (const float*)d_in[0];
    const float* theta = (const float*)d_in[1];
    const float* sigma = (const float*)d_in[2];
    const float* lambd = (const float*)d_in[3];
    const float* gamma = (const float*)d_in[4];
    const float* psi   = (const float*)d_in[5];
    float* out = (float*)d_out;

    prep_kernel<<<CHAN_BLOCKS + 1, 256>>>(x, theta, sigma, lambd, gamma, psi);

    dim3 blk(16, 16);
    dim3 grd(W / TILE_X, H / TILE_Y, BATCH);
    gabor_conv_sym<<<grd, blk>>>(out);

    gabor_conv_fallback<<<1184, 256>>>(out);
}

// round 4
// speedup vs baseline: 2.1132x; 1.1130x over previous
#include <cuda_runtime.h>

#define W 256
#define H 256
#define BATCH 64
#define NF 8
#define KS 15
#define PAD 7

#define TILE_X 64           // 16 threads x 4 px
#define TILE_Y 16
#define SROWS (TILE_Y + KS - 1)   // 30
#define SCOLS (TILE_X + KS - 1)   // 78
#define SSTRIDE 80

// derived-weight layout (floats, all values duplicated for f32x2 broadcast)
// quads: 49 * 16  (5 wp-dup pairs + 3 wm-dup pairs)
#define WQ_COL 784          // 7 * 10  (5 wp-dup)
#define WQ_ROW 854          // 7 * 10
#define WQ_CEN 924          // 10
#define WQ_TOTAL 934

#define CHAN_BLOCKS 4096

typedef unsigned long long ull;

__device__ float g_xs[BATCH * H * W];
__device__ float g_w[KS * KS * NF];    // full weights [tap][filter] (fallback)
__device__ float g_wq[WQ_TOTAL];       // quad-symmetric derived weights
__device__ int   g_flag;               // 1 -> symmetry violated, use fallback

__device__ __forceinline__ ull pk(float a, float b) {
    ull r; asm("mov.b64 %0, {%1, %2};" : "=l"(r) : "f"(a), "f"(b)); return r;
}
__device__ __forceinline__ ull add2(ull a, ull b) {
    ull r; asm("add.rn.f32x2 %0, %1, %2;" : "=l"(r) : "l"(a), "l"(b)); return r;
}
__device__ __forceinline__ ull sub2(ull a, ull b) {
    ull r; asm("sub.rn.f32x2 %0, %1, %2;" : "=l"(r) : "l"(a), "l"(b)); return r;
}
__device__ __forceinline__ void fma2(ull& acc, ull a, ull b) {
    asm("fma.rn.f32x2 %0, %1, %2, %0;" : "+l"(acc) : "l"(a), "l"(b));
}
__device__ __forceinline__ void unpk(float& lo, float& hi, ull v) {
    asm("mov.b64 {%0, %1}, %2;" : "=f"(lo), "=f"(hi) : "l"(v));
}

// ---------------------------------------------------------------------------
// Prep: blocks [0, CHAN_BLOCKS) channel-sum; block CHAN_BLOCKS builds weights.
// ---------------------------------------------------------------------------
__global__ void prep_kernel(const float* __restrict__ x,
                            const float* __restrict__ theta,
                            const float* __restrict__ sigma,
                            const float* __restrict__ lambd,
                            const float* __restrict__ gamma,
                            const float* __restrict__ psi) {
    if (blockIdx.x < CHAN_BLOCKS) {
        int i = blockIdx.x * blockDim.x + threadIdx.x;
        const int plane4 = H * W / 4;
        int b = i / plane4;
        int p = i - b * plane4;
        const float4* xb = (const float4*)x + (size_t)b * 3 * plane4;
        float4 a = xb[p];
        float4 c = xb[p + plane4];
        float4 d = xb[p + 2 * plane4];
        float4 r;
        r.x = a.x + c.x + d.x;
        r.y = a.y + c.y + d.y;
        r.z = a.z + c.z + d.z;
        r.w = a.w + c.w + d.w;
        ((float4*)g_xs)[i] = r;
        return;
    }

    // ---- Gabor weights ----
    __shared__ float s_w[NF][228];
    __shared__ int sflag;
    int tid = threadIdx.x;
    int warp = tid >> 5;
    int lane = tid & 31;
    if (tid == 0) sflag = 0;

    if (warp < NF) {
        int f = warp;
        float th = theta[f];
        float sg = fmaxf(sigma[f], 1.0f);
        float lb = fmaxf(lambd[f], 2.0f);
        float gm = fminf(fmaxf(gamma[f], 0.1f), 1.0f);
        float ps = psi[f];
        float ct = cosf(th), st = sinf(th);
        const float TWO_PI = 6.283185307179586f;
        float inv_sg2 = 1.0f / (sg * sg);
        float gm2 = gm * gm;

        float vals[8];
        float sum = 0.0f;
        #pragma unroll
        for (int k = 0; k < 8; k++) {
            int i = lane + 32 * k;
            float v = 0.0f;
            if (i < KS * KS) {
                int hh = i / KS, ww = i % KS;
                float y = (float)(hh - PAD);
                float xx = (float)(ww - PAD);
                float xt = xx * ct + y * st;
                float yt = -xx * st + y * ct;
                float gaussian = expf(-0.5f * (xt * xt + gm2 * yt * yt) * inv_sg2);
                float sinus = cosf(TWO_PI * xt / lb + ps);
                v = gaussian * sinus;
            }
            vals[k] = v;
            sum += v;
        }
        #pragma unroll
        for (int o = 16; o; o >>= 1) sum += __shfl_xor_sync(0xffffffffu, sum, o);
        float mean = sum * (1.0f / 225.0f);

        float ss = 0.0f;
        #pragma unroll
        for (int k = 0; k < 8; k++) {
            int i = lane + 32 * k;
            if (i < KS * KS) {
                float d = vals[k] - mean;
                ss += d * d;
            }
        }
        #pragma unroll
        for (int o = 16; o; o >>= 1) ss += __shfl_xor_sync(0xffffffffu, ss, o);
        float inv = 1.0f / (sqrtf(ss * (1.0f / 224.0f)) + 1e-8f);

        #pragma unroll
        for (int k = 0; k < 8; k++) {
            int i = lane + 32 * k;
            if (i < KS * KS) s_w[f][i] = (vals[k] - mean) * inv;
        }
    }
    __syncthreads();

    // full weights tap-major (fallback path)
    for (int idx = tid; idx < KS * KS * NF; idx += 256) {
        int i = idx >> 3, f = idx & 7;
        g_w[idx] = s_w[f][i];
    }

    // ---- derived quad-symmetric weights ----
    // filter groups: g -> (f, f') mirror pairs
    const int gf[5] = {0, 1, 2, 3, 4};
    const int gp[5] = {0, 7, 6, 5, 4};
    const float E = 1e-5f;
    int bad = 0;

    // quads: kyp 0..6, kxp 0..6
    for (int idx = tid; idx < 245; idx += 256) {
        int q = idx / 5, g = idx % 5;
        int kyp = q / 7, kxp = q % 7;
        int i1 = kyp * 15 + kxp;
        int i2 = (14 - kyp) * 15 + (14 - kxp);
        int i3 = kyp * 15 + (14 - kxp);
        int i4 = (14 - kyp) * 15 + kxp;
        int f = gf[g], fp = gp[g];
        float f1 = s_w[f][i1], f2 = s_w[f][i2], f3 = s_w[f][i3], f4 = s_w[f][i4];
        float p1 = s_w[fp][i1], p2 = s_w[fp][i2], p3 = s_w[fp][i3], p4 = s_w[fp][i4];
        float af = 0.5f * (f1 + f2), bf = 0.5f * (f3 + f4);
        float ap = 0.5f * (p1 + p2), bp = 0.5f * (p3 + p4);
        float wpf = 0.5f * (af + bf), wmf = 0.5f * (af - bf);
        float wpp = 0.5f * (ap + bp), wmp = 0.5f * (ap - bp);
        float wp = 0.5f * (wpf + wpp), wm = 0.5f * (wmf - wmp);
        if (fabsf(f1 - f2) > E || fabsf(f3 - f4) > E ||
            fabsf(p1 - p2) > E || fabsf(p3 - p4) > E ||
            fabsf(wpf - wpp) > E || fabsf(wmf + wmp) > E) bad = 1;
        g_wq[q * 16 + 2 * g] = wp;
        g_wq[q * 16 + 2 * g + 1] = wp;
        if (g >= 1 && g <= 3) {
            g_wq[q * 16 + 10 + 2 * (g - 1)] = wm;
            g_wq[q * 16 + 10 + 2 * (g - 1) + 1] = wm;
        }
    }

    // kx = 7 column, kyp 0..6
    for (int idx = tid; idx < 35; idx += 256) {
        int kyp = idx / 5, g = idx % 5;
        int i1 = kyp * 15 + 7, i2 = (14 - kyp) * 15 + 7;
        int f = gf[g], fp = gp[g];
        float f1 = s_w[f][i1], f2 = s_w[f][i2];
        float p1 = s_w[fp][i1], p2 = s_w[fp][i2];
        float af = 0.5f * (f1 + f2), ap = 0.5f * (p1 + p2);
        float wp = 0.5f * (af + ap);
        if (fabsf(f1 - f2) > E || fabsf(p1 - p2) > E || fabsf(af - ap) > E) bad = 1;
        g_wq[WQ_COL + kyp * 10 + 2 * g] = wp;
        g_wq[WQ_COL + kyp * 10 + 2 * g + 1] = wp;
    }

    // ky = 7 row, kxp 0..6
    for (int idx = tid; idx < 35; idx += 256) {
        int kxp = idx / 5, g = idx % 5;
        int i1 = 105 + kxp, i3 = 105 + 14 - kxp;
        int f = gf[g], fp = gp[g];
        float f1 = s_w[f][i1], f3 = s_w[f][i3];
        float p1 = s_w[fp][i1], p3 = s_w[fp][i3];
        float af = 0.5f * (f1 + f3), ap = 0.5f * (p1 + p3);
        float wp = 0.5f * (af + ap);
        if (fabsf(f1 - f3) > E || fabsf(p1 - p3) > E || fabsf(af - ap) > E) bad = 1;
        g_wq[WQ_ROW + kxp * 10 + 2 * g] = wp;
        g_wq[WQ_ROW + kxp * 10 + 2 * g + 1] = wp;
    }

    // center (7,7)
    if (tid < 5) {
        int g = tid;
        int f = gf[g], fp = gp[g];
        float f1 = s_w[f][112], p1 = s_w[fp][112];
        float wp = 0.5f * (f1 + p1);
        if (fabsf(f1 - p1) > E) bad = 1;
        g_wq[WQ_CEN + 2 * g] = wp;
        g_wq[WQ_CEN + 2 * g + 1] = wp;
    }

    if (bad) atomicOr(&sflag, 1);
    __syncthreads();
    if (tid == 0) g_flag = sflag;
}

// ---------------------------------------------------------------------------
// Fast conv: full 4-fold symmetry (point + cross-filter x-mirror).
// Block (16,16), tile 64x16, 4 px/thread, pixels in f32x2 lanes.
// Per quad (kyp,kxp): u = tb[+kx]+tb[-kx], v = td[+kx]-td[-kx],
// then 5 P-FFMA2 + 3 Q-FFMA2 cover all 8 filters.
// ---------------------------------------------------------------------------
__global__ void __launch_bounds__(256, 2)
gabor_conv_sym(float* __restrict__ out) {
    if (g_flag != 0) return;   // fallback kernel handles it

    __shared__ __align__(16) float s_in[SROWS * SSTRIDE];
    __shared__ __align__(16) float s_wq[WQ_TOTAL];

    int txq = threadIdx.x;        // 0..15 -> 4 px each
    int tyr = threadIdx.y;        // 0..15
    int tid = txq + tyr * 16;
    int x0 = blockIdx.x * TILE_X;
    int y0 = blockIdx.y * TILE_Y;
    int b  = blockIdx.z;

    for (int i = tid; i < WQ_TOTAL; i += 256) s_wq[i] = g_wq[i];

    const float* xs = g_xs + (size_t)b * H * W;
    for (int i = tid; i < SROWS * SCOLS; i += 256) {
        int r = i / SCOLS, c = i - r * SCOLS;
        int gy = y0 - PAD + r;
        int gx = x0 - PAD + c;
        float v = 0.0f;
        if (gy >= 0 && gy < H && gx >= 0 && gx < W) v = xs[gy * W + gx];
        s_in[r * SSTRIDE + c] = v;
    }
    __syncthreads();

    int c0 = txq * 4;
    ull P[5][2], Q[3][2];
    #pragma unroll
    for (int g = 0; g < 5; g++) { P[g][0] = 0ull; P[g][1] = 0ull; }
    #pragma unroll
    for (int g = 0; g < 3; g++) { Q[g][0] = 0ull; Q[g][1] = 0ull; }

    #pragma unroll 1
    for (int kyp = 0; kyp < 7; kyp++) {
        const float4* tp = (const float4*)(s_in + (tyr + kyp) * SSTRIDE + c0);
        const float4* bp = (const float4*)(s_in + (tyr + 14 - kyp) * SSTRIDE + c0);
        float tb[20], td[20];
        #pragma unroll
        for (int j = 0; j < 5; j++) {
            float4 tv = tp[j];
            float4 bv = bp[j];
            tb[4 * j + 0] = tv.x + bv.x;  td[4 * j + 0] = tv.x - bv.x;
            tb[4 * j + 1] = tv.y + bv.y;  td[4 * j + 1] = tv.y - bv.y;
            tb[4 * j + 2] = tv.z + bv.z;  td[4 * j + 2] = tv.z - bv.z;
            tb[4 * j + 3] = tv.w + bv.w;  td[4 * j + 3] = tv.w - bv.w;
        }
        const float* wq = s_wq + kyp * 7 * 16;
        #pragma unroll
        for (int kxp = 0; kxp < 7; kxp++) {
            const ull* wv = (const ull*)(wq + kxp * 16);
            ull w0 = wv[0], w1 = wv[1], w2 = wv[2], w3 = wv[3], w4 = wv[4];
            ull m0 = wv[5], m1 = wv[6], m2 = wv[7];
            #pragma unroll
            for (int pp = 0; pp < 2; pp++) {
                int o = 2 * pp;
                ull u = add2(pk(tb[o + kxp], tb[o + kxp + 1]),
                             pk(tb[o + 14 - kxp], tb[o + 15 - kxp]));
                ull v = sub2(pk(td[o + kxp], td[o + kxp + 1]),
                             pk(td[o + 14 - kxp], td[o + 15 - kxp]));
                fma2(P[0][pp], u, w0);
                fma2(P[1][pp], u, w1);
                fma2(P[2][pp], u, w2);
                fma2(P[3][pp], u, w3);
                fma2(P[4][pp], u, w4);
                fma2(Q[0][pp], v, m0);
                fma2(Q[1][pp], v, m1);
                fma2(Q[2][pp], v, m2);
            }
        }
        // kx = 7 column (P only)
        const ull* wc = (const ull*)(s_wq + WQ_COL + kyp * 10);
        ull c0w = wc[0], c1w = wc[1], c2w = wc[2], c3w = wc[3], c4w = wc[4];
        #pragma unroll
        for (int pp = 0; pp < 2; pp++) {
            ull u = pk(tb[2 * pp + 7], tb[2 * pp + 8]);
            fma2(P[0][pp], u, c0w);
            fma2(P[1][pp], u, c1w);
            fma2(P[2][pp], u, c2w);
            fma2(P[3][pp], u, c3w);
            fma2(P[4][pp], u, c4w);
        }
    }

    // ky = 7 row
    {
        const float4* rp = (const float4*)(s_in + (tyr + 7) * SSTRIDE + c0);
        float r[20];
        #pragma unroll
        for (int j = 0; j < 5; j++) {
            float4 v = rp[j];
            r[4 * j + 0] = v.x; r[4 * j + 1] = v.y;
            r[4 * j + 2] = v.z; r[4 * j + 3] = v.w;
        }
        #pragma unroll
        for (int kxp = 0; kxp < 7; kxp++) {
            const ull* wr = (const ull*)(s_wq + WQ_ROW + kxp * 10);
            ull r0w = wr[0], r1w = wr[1], r2w = wr[2], r3w = wr[3], r4w = wr[4];
            #pragma unroll
            for (int pp = 0; pp < 2; pp++) {
                int o = 2 * pp;
                ull u = add2(pk(r[o + kxp], r[o + kxp + 1]),
                             pk(r[o + 14 - kxp], r[o + 15 - kxp]));
                fma2(P[0][pp], u, r0w);
                fma2(P[1][pp], u, r1w);
                fma2(P[2][pp], u, r2w);
                fma2(P[3][pp], u, r3w);
                fma2(P[4][pp], u, r4w);
            }
        }
        // center tap
        const ull* wn = (const ull*)(s_wq + WQ_CEN);
        ull n0 = wn[0], n1 = wn[1], n2 = wn[2], n3 = wn[3], n4 = wn[4];
        #pragma unroll
        for (int pp = 0; pp < 2; pp++) {
            ull u = pk(r[2 * pp + 7], r[2 * pp + 8]);
            fma2(P[0][pp], u, n0);
            fma2(P[1][pp], u, n1);
            fma2(P[2][pp], u, n2);
            fma2(P[3][pp], u, n3);
            fma2(P[4][pp], u, n4);
        }
    }

    // epilogue: unpack and reconstruct 8 filters
    float p[5][4], q[3][4];
    #pragma unroll
    for (int g = 0; g < 5; g++) {
        unpk(p[g][0], p[g][1], P[g][0]);
        unpk(p[g][2], p[g][3], P[g][1]);
    }
    #pragma unroll
    for (int g = 0; g < 3; g++) {
        unpk(q[g][0], q[g][1], Q[g][0]);
        unpk(q[g][2], q[g][3], Q[g][1]);
    }

    float r[8][4];   // [filter][pixel]
    #pragma unroll
    for (int px = 0; px < 4; px++) {
        r[0][px] = p[0][px];
        r[4][px] = p[4][px];
        r[1][px] = p[1][px] + q[0][px];
        r[7][px] = p[1][px] - q[0][px];
        r[2][px] = p[2][px] + q[1][px];
        r[6][px] = p[2][px] - q[1][px];
        r[3][px] = p[3][px] + q[2][px];
        r[5][px] = p[3][px] - q[2][px];
    }

    float* ob = out + (size_t)b * NF * H * W;
    int y = y0 + tyr;
    int xb = x0 + c0;
    #pragma unroll
    for (int f = 0; f < NF; f++) {
        float4 v = make_float4(r[f][0], r[f][1], r[f][2], r[f][3]);
        *(float4*)(ob + f * H * W + y * W + xb) = v;
    }
}

// ---------------------------------------------------------------------------
// Fallback: generic direct conv (runs only if weights are not symmetric).
// ---------------------------------------------------------------------------
__global__ void gabor_conv_fallback(float* __restrict__ out) {
    if (g_flag == 0) return;
    int total = BATCH * NF * H * W;
    for (int idx = blockIdx.x * blockDim.x + threadIdx.x; idx < total;
         idx += gridDim.x * blockDim.x) {
        int x = idx & (W - 1);
        int y = (idx >> 8) & (H - 1);
        int f = (idx >> 16) & (NF - 1);
        int b = idx >> 19;
        const float* xs = g_xs + (size_t)b * H * W;
        float acc = 0.0f;
        for (int ky = 0; ky < KS; ky++) {
            int gy = y - PAD + ky;
            if (gy < 0 || gy >= H) continue;
            for (int kx = 0; kx < KS; kx++) {
                int gx = x - PAD + kx;
                if (gx < 0 || gx >= W) continue;
                acc += g_w[(ky * KS + kx) * NF + f] * xs[gy * W + gx];
            }
        }
        out[idx] = acc;
    }
}

// ---------------------------------------------------------------------------
extern "C" void kernel_launch(void* const* d_in, const int* in_sizes, int n_in,
                              void* d_out, int out_size) {
    const float* x     = (const float*)d_in[0];
    const float* theta = (const float*)d_in[1];
    const float* sigma = (const float*)d_in[2];
    const float* lambd = (const float*)d_in[3];
    const float* gamma = (const float*)d_in[4];
    const float* psi   = (const float*)d_in[5];
    float* out = (float*)d_out;

    prep_kernel<<<CHAN_BLOCKS + 1, 256>>>(x, theta, sigma, lambd, gamma, psi);

    dim3 blk(16, 16);
    dim3 grd(W / TILE_X, H / TILE_Y, BATCH);
    gabor_conv_sym<<<grd, blk>>>(out);

    gabor_conv_fallback<<<1184, 256>>>(out);
}

// round 5
// speedup vs baseline: 2.5054x; 1.1856x over previous
#include <cuda_runtime.h>

#define W 256
#define H 256
#define BATCH 64
#define NF 8
#define KS 15
#define PAD 7

#define TILE_X 64           // 16 threads x 4 px
#define TILE_Y 16
#define SROWS (TILE_Y + KS - 1)   // 30
#define SCOLS (TILE_X + KS - 1)   // 78
#define SSTRIDE 80

// derived-weight layout (floats, all values duplicated for f32x2 broadcast)
#define WQ_COL 784          // 49 quads * 16
#define WQ_ROW 854          // + 7*10
#define WQ_CEN 924          // + 7*10
#define WQ_TOTAL 934

#define CHAN_BLOCKS 4096

typedef unsigned long long ull;

__device__ float g_xs[BATCH * H * W];
__device__ float g_w[KS * KS * NF];    // full weights [tap][filter] (fallback)
__device__ float g_wq[WQ_TOTAL];       // staging for constant copy
__device__ int   g_flag;               // 1 -> symmetry violated, use fallback

__constant__ __align__(16) float c_wq[WQ_TOTAL];

__device__ __forceinline__ ull pk(float a, float b) {
    ull r; asm("mov.b64 %0, {%1, %2};" : "=l"(r) : "f"(a), "f"(b)); return r;
}
__device__ __forceinline__ ull add2(ull a, ull b) {
    ull r; asm("add.rn.f32x2 %0, %1, %2;" : "=l"(r) : "l"(a), "l"(b)); return r;
}
__device__ __forceinline__ ull sub2(ull a, ull b) {
    ull r; asm("sub.rn.f32x2 %0, %1, %2;" : "=l"(r) : "l"(a), "l"(b)); return r;
}
__device__ __forceinline__ void fma2(ull& acc, ull a, ull b) {
    asm("fma.rn.f32x2 %0, %1, %2, %0;" : "+l"(acc) : "l"(a), "l"(b));
}
__device__ __forceinline__ void unpk(float& lo, float& hi, ull v) {
    asm("mov.b64 {%0, %1}, %2;" : "=f"(lo), "=f"(hi) : "l"(v));
}

// ---------------------------------------------------------------------------
// Prep: blocks [0, CHAN_BLOCKS) channel-sum; block CHAN_BLOCKS builds weights.
// ---------------------------------------------------------------------------
__global__ void prep_kernel(const float* __restrict__ x,
                            const float* __restrict__ theta,
                            const float* __restrict__ sigma,
                            const float* __restrict__ lambd,
                            const float* __restrict__ gamma,
                            const float* __restrict__ psi) {
    if (blockIdx.x < CHAN_BLOCKS) {
        int i = blockIdx.x * blockDim.x + threadIdx.x;
        const int plane4 = H * W / 4;
        int b = i / plane4;
        int p = i - b * plane4;
        const float4* xb = (const float4*)x + (size_t)b * 3 * plane4;
        float4 a = xb[p];
        float4 c = xb[p + plane4];
        float4 d = xb[p + 2 * plane4];
        float4 r;
        r.x = a.x + c.x + d.x;
        r.y = a.y + c.y + d.y;
        r.z = a.z + c.z + d.z;
        r.w = a.w + c.w + d.w;
        ((float4*)g_xs)[i] = r;
        return;
    }

    // ---- Gabor weights ----
    __shared__ float s_w[NF][228];
    __shared__ int sflag;
    int tid = threadIdx.x;
    int warp = tid >> 5;
    int lane = tid & 31;
    if (tid == 0) sflag = 0;

    if (warp < NF) {
        int f = warp;
        float th = theta[f];
        float sg = fmaxf(sigma[f], 1.0f);
        float lb = fmaxf(lambd[f], 2.0f);
        float gm = fminf(fmaxf(gamma[f], 0.1f), 1.0f);
        float ps = psi[f];
        float ct = cosf(th), st = sinf(th);
        const float TWO_PI = 6.283185307179586f;
        float inv_sg2 = 1.0f / (sg * sg);
        float gm2 = gm * gm;

        float vals[8];
        float sum = 0.0f;
        #pragma unroll
        for (int k = 0; k < 8; k++) {
            int i = lane + 32 * k;
            float v = 0.0f;
            if (i < KS * KS) {
                int hh = i / KS, ww = i % KS;
                float y = (float)(hh - PAD);
                float xx = (float)(ww - PAD);
                float xt = xx * ct + y * st;
                float yt = -xx * st + y * ct;
                float gaussian = expf(-0.5f * (xt * xt + gm2 * yt * yt) * inv_sg2);
                float sinus = cosf(TWO_PI * xt / lb + ps);
                v = gaussian * sinus;
            }
            vals[k] = v;
            sum += v;
        }
        #pragma unroll
        for (int o = 16; o; o >>= 1) sum += __shfl_xor_sync(0xffffffffu, sum, o);
        float mean = sum * (1.0f / 225.0f);

        float ss = 0.0f;
        #pragma unroll
        for (int k = 0; k < 8; k++) {
            int i = lane + 32 * k;
            if (i < KS * KS) {
                float d = vals[k] - mean;
                ss += d * d;
            }
        }
        #pragma unroll
        for (int o = 16; o; o >>= 1) ss += __shfl_xor_sync(0xffffffffu, ss, o);
        float inv = 1.0f / (sqrtf(ss * (1.0f / 224.0f)) + 1e-8f);

        #pragma unroll
        for (int k = 0; k < 8; k++) {
            int i = lane + 32 * k;
            if (i < KS * KS) s_w[f][i] = (vals[k] - mean) * inv;
        }
    }
    __syncthreads();

    // full weights tap-major (fallback path)
    for (int idx = tid; idx < KS * KS * NF; idx += 256) {
        int i = idx >> 3, f = idx & 7;
        g_w[idx] = s_w[f][i];
    }

    // ---- derived quad-symmetric weights ----
    const int gf[5] = {0, 1, 2, 3, 4};
    const int gp[5] = {0, 7, 6, 5, 4};
    const float E = 1e-5f;
    int bad = 0;

    for (int idx = tid; idx < 245; idx += 256) {
        int q = idx / 5, g = idx % 5;
        int kyp = q / 7, kxp = q % 7;
        int i1 = kyp * 15 + kxp;
        int i2 = (14 - kyp) * 15 + (14 - kxp);
        int i3 = kyp * 15 + (14 - kxp);
        int i4 = (14 - kyp) * 15 + kxp;
        int f = gf[g], fp = gp[g];
        float f1 = s_w[f][i1], f2 = s_w[f][i2], f3 = s_w[f][i3], f4 = s_w[f][i4];
        float p1 = s_w[fp][i1], p2 = s_w[fp][i2], p3 = s_w[fp][i3], p4 = s_w[fp][i4];
        float af = 0.5f * (f1 + f2), bf = 0.5f * (f3 + f4);
        float ap = 0.5f * (p1 + p2), bp = 0.5f * (p3 + p4);
        float wpf = 0.5f * (af + bf), wmf = 0.5f * (af - bf);
        float wpp = 0.5f * (ap + bp), wmp = 0.5f * (ap - bp);
        float wp = 0.5f * (wpf + wpp), wm = 0.5f * (wmf - wmp);
        if (fabsf(f1 - f2) > E || fabsf(f3 - f4) > E ||
            fabsf(p1 - p2) > E || fabsf(p3 - p4) > E ||
            fabsf(wpf - wpp) > E || fabsf(wmf + wmp) > E) bad = 1;
        g_wq[q * 16 + 2 * g] = wp;
        g_wq[q * 16 + 2 * g + 1] = wp;
        if (g >= 1 && g <= 3) {
            g_wq[q * 16 + 10 + 2 * (g - 1)] = wm;
            g_wq[q * 16 + 10 + 2 * (g - 1) + 1] = wm;
        }
    }

    for (int idx = tid; idx < 35; idx += 256) {
        int kyp = idx / 5, g = idx % 5;
        int i1 = kyp * 15 + 7, i2 = (14 - kyp) * 15 + 7;
        int f = gf[g], fp = gp[g];
        float f1 = s_w[f][i1], f2 = s_w[f][i2];
        float p1 = s_w[fp][i1], p2 = s_w[fp][i2];
        float af = 0.5f * (f1 + f2), ap = 0.5f * (p1 + p2);
        float wp = 0.5f * (af + ap);
        if (fabsf(f1 - f2) > E || fabsf(p1 - p2) > E || fabsf(af - ap) > E) bad = 1;
        g_wq[WQ_COL + kyp * 10 + 2 * g] = wp;
        g_wq[WQ_COL + kyp * 10 + 2 * g + 1] = wp;
    }

    for (int idx = tid; idx < 35; idx += 256) {
        int kxp = idx / 5, g = idx % 5;
        int i1 = 105 + kxp, i3 = 105 + 14 - kxp;
        int f = gf[g], fp = gp[g];
        float f1 = s_w[f][i1], f3 = s_w[f][i3];
        float p1 = s_w[fp][i1], p3 = s_w[fp][i3];
        float af = 0.5f * (f1 + f3), ap = 0.5f * (p1 + p3);
        float wp = 0.5f * (af + ap);
        if (fabsf(f1 - f3) > E || fabsf(p1 - p3) > E || fabsf(af - ap) > E) bad = 1;
        g_wq[WQ_ROW + kxp * 10 + 2 * g] = wp;
        g_wq[WQ_ROW + kxp * 10 + 2 * g + 1] = wp;
    }

    if (tid < 5) {
        int g = tid;
        int f = gf[g], fp = gp[g];
        float f1 = s_w[f][112], p1 = s_w[fp][112];
        float wp = 0.5f * (f1 + p1);
        if (fabsf(f1 - p1) > E) bad = 1;
        g_wq[WQ_CEN + 2 * g] = wp;
        g_wq[WQ_CEN + 2 * g + 1] = wp;
    }

    if (bad) atomicOr(&sflag, 1);
    __syncthreads();
    if (tid == 0) g_flag = sflag;
}

// ---------------------------------------------------------------------------
// Fast conv: 4-fold symmetry, shifted packed windows, constant weights.
// Block (16,16), tile 64x16, 4 px/thread in two f32x2 lanes pairs.
// ---------------------------------------------------------------------------
__global__ void __launch_bounds__(256, 2)
gabor_conv_sym(float* __restrict__ out) {
    if (g_flag != 0) return;

    __shared__ __align__(16) float s_in[SROWS * SSTRIDE];

    int txq = threadIdx.x;        // 0..15 -> 4 px each
    int tyr = threadIdx.y;        // 0..15
    int tid = txq + tyr * 16;
    int x0 = blockIdx.x * TILE_X;
    int y0 = blockIdx.y * TILE_Y;
    int b  = blockIdx.z;

    const float* xs = g_xs + (size_t)b * H * W;
    for (int i = tid; i < SROWS * SCOLS; i += 256) {
        int r = i / SCOLS, c = i - r * SCOLS;
        int gy = y0 - PAD + r;
        int gx = x0 - PAD + c;
        float v = 0.0f;
        if (gy >= 0 && gy < H && gx >= 0 && gx < W) v = xs[gy * W + gx];
        s_in[r * SSTRIDE + c] = v;
    }
    __syncthreads();

    int c0 = txq * 4;
    ull P[5][2], Q[3][2];
    #pragma unroll
    for (int g = 0; g < 5; g++) { P[g][0] = 0ull; P[g][1] = 0ull; }
    #pragma unroll
    for (int g = 0; g < 3; g++) { Q[g][0] = 0ull; Q[g][1] = 0ull; }

    #pragma unroll 1
    for (int kyp = 0; kyp < 7; kyp++) {
        const float4* tp = (const float4*)(s_in + (tyr + kyp) * SSTRIDE + c0);
        const float4* bp = (const float4*)(s_in + (tyr + 14 - kyp) * SSTRIDE + c0);

        // packed shifted windows: tbP[i] = (t+b)[i..i+1], tdP[i] = (t-b)[i..i+1]
        ull tbP[17], tdP[17];
        #pragma unroll
        for (int j = 0; j < 5; j++) {
            float4 tv = tp[j];
            float4 bv = bp[j];
            ull t0 = pk(tv.x, tv.y), t1 = pk(tv.z, tv.w);
            ull b0 = pk(bv.x, bv.y), b1 = pk(bv.z, bv.w);
            tbP[4 * j] = add2(t0, b0);
            tdP[4 * j] = sub2(t0, b0);
            if (4 * j + 2 <= 16) {
                tbP[4 * j + 2] = add2(t1, b1);
                tdP[4 * j + 2] = sub2(t1, b1);
            }
        }
        // odd offsets from even halves
        #pragma unroll
        for (int k = 0; k < 8; k++) {
            float l0, h0, l1, h1;
            unpk(l0, h0, tbP[2 * k]); unpk(l1, h1, tbP[2 * k + 2]);
            tbP[2 * k + 1] = pk(h0, l1);
            unpk(l0, h0, tdP[2 * k]); unpk(l1, h1, tdP[2 * k + 2]);
            tdP[2 * k + 1] = pk(h0, l1);
        }

        const float* wq = c_wq + kyp * 112;
        #pragma unroll
        for (int kxp = 0; kxp < 7; kxp++) {
            const ull* wv = (const ull*)(wq + kxp * 16);
            ull w0 = wv[0], w1 = wv[1], w2 = wv[2], w3 = wv[3], w4 = wv[4];
            ull m0 = wv[5], m1 = wv[6], m2 = wv[7];
            #pragma unroll
            for (int pp = 0; pp < 2; pp++) {
                int o = 2 * pp;
                ull u = add2(tbP[o + kxp], tbP[o + 14 - kxp]);
                ull v = sub2(tdP[o + kxp], tdP[o + 14 - kxp]);
                fma2(P[0][pp], u, w0);
                fma2(P[1][pp], u, w1);
                fma2(P[2][pp], u, w2);
                fma2(P[3][pp], u, w3);
                fma2(P[4][pp], u, w4);
                fma2(Q[0][pp], v, m0);
                fma2(Q[1][pp], v, m1);
                fma2(Q[2][pp], v, m2);
            }
        }
        // kx = 7 column (P only)
        const ull* wc = (const ull*)(c_wq + WQ_COL + kyp * 10);
        ull c0w = wc[0], c1w = wc[1], c2w = wc[2], c3w = wc[3], c4w = wc[4];
        #pragma unroll
        for (int pp = 0; pp < 2; pp++) {
            ull u = tbP[2 * pp + 7];
            fma2(P[0][pp], u, c0w);
            fma2(P[1][pp], u, c1w);
            fma2(P[2][pp], u, c2w);
            fma2(P[3][pp], u, c3w);
            fma2(P[4][pp], u, c4w);
        }
    }

    // ky = 7 row
    {
        const float4* rp = (const float4*)(s_in + (tyr + 7) * SSTRIDE + c0);
        ull rP[17];
        float rf[20];
        #pragma unroll
        for (int j = 0; j < 5; j++) {
            float4 v = rp[j];
            rf[4 * j + 0] = v.x; rf[4 * j + 1] = v.y;
            rf[4 * j + 2] = v.z; rf[4 * j + 3] = v.w;
        }
        #pragma unroll
        for (int i = 0; i < 17; i++) rP[i] = pk(rf[i], rf[i + 1]);

        #pragma unroll
        for (int kxp = 0; kxp < 7; kxp++) {
            const ull* wr = (const ull*)(c_wq + WQ_ROW + kxp * 10);
            ull r0w = wr[0], r1w = wr[1], r2w = wr[2], r3w = wr[3], r4w = wr[4];
            #pragma unroll
            for (int pp = 0; pp < 2; pp++) {
                int o = 2 * pp;
                ull u = add2(rP[o + kxp], rP[o + 14 - kxp]);
                fma2(P[0][pp], u, r0w);
                fma2(P[1][pp], u, r1w);
                fma2(P[2][pp], u, r2w);
                fma2(P[3][pp], u, r3w);
                fma2(P[4][pp], u, r4w);
            }
        }
        const ull* wn = (const ull*)(c_wq + WQ_CEN);
        ull n0 = wn[0], n1 = wn[1], n2 = wn[2], n3 = wn[3], n4 = wn[4];
        #pragma unroll
        for (int pp = 0; pp < 2; pp++) {
            ull u = rP[2 * pp + 7];
            fma2(P[0][pp], u, n0);
            fma2(P[1][pp], u, n1);
            fma2(P[2][pp], u, n2);
            fma2(P[3][pp], u, n3);
            fma2(P[4][pp], u, n4);
        }
    }

    // epilogue
    float p[5][4], q[3][4];
    #pragma unroll
    for (int g = 0; g < 5; g++) {
        unpk(p[g][0], p[g][1], P[g][0]);
        unpk(p[g][2], p[g][3], P[g][1]);
    }
    #pragma unroll
    for (int g = 0; g < 3; g++) {
        unpk(q[g][0], q[g][1], Q[g][0]);
        unpk(q[g][2], q[g][3], Q[g][1]);
    }

    float r[8][4];
    #pragma unroll
    for (int px = 0; px < 4; px++) {
        r[0][px] = p[0][px];
        r[4][px] = p[4][px];
        r[1][px] = p[1][px] + q[0][px];
        r[7][px] = p[1][px] - q[0][px];
        r[2][px] = p[2][px] + q[1][px];
        r[6][px] = p[2][px] - q[1][px];
        r[3][px] = p[3][px] + q[2][px];
        r[5][px] = p[3][px] - q[2][px];
    }

    float* ob = out + (size_t)b * NF * H * W;
    int y = y0 + tyr;
    int xb = x0 + c0;
    #pragma unroll
    for (int f = 0; f < NF; f++) {
        float4 v = make_float4(r[f][0], r[f][1], r[f][2], r[f][3]);
        *(float4*)(ob + f * H * W + y * W + xb) = v;
    }
}

// ---------------------------------------------------------------------------
// Fallback: generic direct conv (runs only if weights are not symmetric).
// ---------------------------------------------------------------------------
__global__ void gabor_conv_fallback(float* __restrict__ out) {
    if (g_flag == 0) return;
    int total = BATCH * NF * H * W;
    for (int idx = blockIdx.x * blockDim.x + threadIdx.x; idx < total;
         idx += gridDim.x * blockDim.x) {
        int x = idx & (W - 1);
        int y = (idx >> 8) & (H - 1);
        int f = (idx >> 16) & (NF - 1);
        int b = idx >> 19;
        const float* xs = g_xs + (size_t)b * H * W;
        float acc = 0.0f;
        for (int ky = 0; ky < KS; ky++) {
            int gy = y - PAD + ky;
            if (gy < 0 || gy >= H) continue;
            for (int kx = 0; kx < KS; kx++) {
                int gx = x - PAD + kx;
                if (gx < 0 || gx >= W) continue;
                acc += g_w[(ky * KS + kx) * NF + f] * xs[gy * W + gx];
            }
        }
        out[idx] = acc;
    }
}

// ---------------------------------------------------------------------------
extern "C" void kernel_launch(void* const* d_in, const int* in_sizes, int n_in,
                              void* d_out, int out_size) {
    const float* x     = (const float*)d_in[0];
    const float* theta = (const float*)d_in[1];
    const float* sigma = (const float*)d_in[2];
    const float* lambd = (const float*)d_in[3];
    const float* gamma = (const float*)d_in[4];
    const float* psi   = (const float*)d_in[5];
    float* out = (float*)d_out;

    prep_kernel<<<CHAN_BLOCKS + 1, 256>>>(x, theta, sigma, lambd, gamma, psi);

    // stage derived weights into constant bank (D2D copy, graph-capturable)
    void* src = nullptr;
    cudaGetSymbolAddress(&src, g_wq);
    cudaMemcpyToSymbolAsync(c_wq, src, WQ_TOTAL * sizeof(float), 0,
                            cudaMemcpyDeviceToDevice, 0);

    dim3 blk(16, 16);
    dim3 grd(W / TILE_X, H / TILE_Y, BATCH);
    gabor_conv_sym<<<grd, blk>>>(out);

    gabor_conv_fallback<<<1184, 256>>>(out);
}